// round 2
// baseline (speedup 1.0000x reference)
#include <cuda_runtime.h>

// Problem constants (fixed by the reference setup)
#define LSEQ   768
#define BATCH  2
#define N_MSA  4
#define DM     128
#define NREL   63   // 2*MAX_LEN - 1

// Scratch tables (device globals — no allocation allowed)
__device__ float g_Ptab[5][DM];   // masked_emb[t] @ W_proj[:64, :]
__device__ float g_Qtab[5][DM];   // masked_emb[t] @ W_proj[64:, :]
__device__ float g_R[NREL][DM];   // W_pos[r] + b_proj + b_pos

// ---------------------------------------------------------------------------
// Table setup: 68 tiny blocks. Blocks 0..4 -> Ptab/Qtab row t,
// blocks 5..67 -> R row (blockIdx-5).
// ---------------------------------------------------------------------------
__global__ void setup_kernel(const float* __restrict__ emb,
                             const float* __restrict__ W_proj,
                             const float* __restrict__ b_proj,
                             const float* __restrict__ W_pos,
                             const float* __restrict__ b_pos) {
    int d = threadIdx.x;          // 0..127
    int task = blockIdx.x;
    if (task < 5) {
        int t = task;
        float pt = 0.f, qt = 0.f;
        if (t != 0) {             // token 0 is masked to zero
            #pragma unroll 16
            for (int k = 0; k < 64; k++) {
                float ek = emb[t * 64 + k];
                pt = fmaf(ek, W_proj[k * DM + d], pt);
                qt = fmaf(ek, W_proj[(64 + k) * DM + d], qt);
            }
        }
        g_Ptab[t][d] = pt;
        g_Qtab[t][d] = qt;
    } else {
        int r = task - 5;
        g_R[r][d] = W_pos[r * DM + d] + b_proj[d] + b_pos[d];
    }
}

// ---------------------------------------------------------------------------
// Main kernel: one block per (b, i). 768*128 fp32 = 393 KB coalesced
// streaming stores per block. rel saturates outside |i-j|<31, so the R term
// is folded into per-token tables for the two saturated regions:
//   j <= i-31 : rel=62  -> s_lo[t] = CT[t] + R[62]   (1 LDS per store)
//   j >= i+31 : rel=0   -> s_hi[t] = CT[t] + R[0]    (1 LDS per store)
//   else      :            s_mid[t] + R[i-j+31] from L2 (61 rows per block)
// where CT[t] = Ptab[seq[i]] + Qtab[t].
// ---------------------------------------------------------------------------
__global__ __launch_bounds__(256, 8) void pair_kernel(const int* __restrict__ msa,
                                                      float* __restrict__ out) {
    __shared__ int    s_seq[LSEQ];
    __shared__ float4 s_lo [5 * 32];
    __shared__ float4 s_mid[5 * 32];
    __shared__ float4 s_hi [5 * 32];

    int bx  = blockIdx.x;               // b*LSEQ + i
    int b   = (bx >= LSEQ) ? 1 : 0;
    int i   = bx - b * LSEQ;
    int tid = threadIdx.x;

    // Load this batch's sequence (row 0 of the MSA) into shared
    const int* seq = msa + (size_t)b * N_MSA * LSEQ;
    for (int k = tid; k < LSEQ; k += 256) s_seq[k] = seq[k];
    __syncthreads();

    int si   = s_seq[i];
    int lane = tid & 31;

    // Build fused tables (160 threads: t = tid>>5, lane covers d as float4)
    if (tid < 5 * 32) {
        int t = tid >> 5;
        float4 p   = ((const float4*)g_Ptab)[si * 32 + lane];
        float4 q   = ((const float4*)g_Qtab)[t  * 32 + lane];
        float4 r0  = ((const float4*)g_R)[ 0 * 32 + lane];
        float4 r62 = ((const float4*)g_R)[62 * 32 + lane];
        float4 c = make_float4(p.x + q.x, p.y + q.y, p.z + q.z, p.w + q.w);
        s_mid[tid] = c;
        s_lo [tid] = make_float4(c.x + r62.x, c.y + r62.y, c.z + r62.z, c.w + r62.w);
        s_hi [tid] = make_float4(c.x + r0.x,  c.y + r0.y,  c.z + r0.z,  c.w + r0.w);
    }
    __syncthreads();

    int warp = tid >> 5;
    float4* outp = (float4*)out + (size_t)bx * LSEQ * 32;
    const float4* gR4 = (const float4*)g_R;

    int jloEnd = i - 30;   // j < jloEnd  -> rel = 62
    int jhiBeg = i + 31;   // j >= jhiBeg -> rel = 0

    for (int j = warp; j < LSEQ; j += 8) {
        int sj = s_seq[j];                      // warp-uniform broadcast
        float4 v;
        if (j < jloEnd) {                       // warp-uniform branch
            v = s_lo[sj * 32 + lane];
        } else if (j >= jhiBeg) {
            v = s_hi[sj * 32 + lane];
        } else {
            float4 c = s_mid[sj * 32 + lane];
            float4 r = __ldg(&gR4[(i - j + 31) * 32 + lane]);
            v = make_float4(c.x + r.x, c.y + r.y, c.z + r.z, c.w + r.w);
        }
        __stcs(&outp[(size_t)j * 32 + lane], v);
    }
}

extern "C" void kernel_launch(void* const* d_in, const int* in_sizes, int n_in,
                              void* d_out, int out_size) {
    const int*   msa    = (const int*)  d_in[0];  // msa_tokens (B, N_MSA, L) int32
    const float* emb    = (const float*)d_in[1];  // (5, 64)
    const float* W_proj = (const float*)d_in[2];  // (128, 128)
    const float* b_proj = (const float*)d_in[3];  // (128,)
    const float* W_pos  = (const float*)d_in[4];  // (63, 128)
    const float* b_pos  = (const float*)d_in[5];  // (128,)
    float* out = (float*)d_out;                   // (B, L, L, 128) fp32

    setup_kernel<<<5 + NREL, DM>>>(emb, W_proj, b_proj, W_pos, b_pos);
    pair_kernel<<<BATCH * LSEQ, 256>>>(msa, out);
}